// round 15
// baseline (speedup 1.0000x reference)
#include <cuda_runtime.h>
#include <cuda_bf16.h>
#include <cuda_fp16.h>
#include <math.h>
#include <stdint.h>

// Problem shapes (fixed): B=4, S=2048, D=1024, H=1024
#define PB 4
#define PS 2048
#define PD 1024
#define PH 1024
#define PM (PB * PS)          // 8192 rows
#define EPSQ 1e-8f

// scan decomposition: 16 chunks x 8 subs x 16 elements = 2048 = S
#define NC 16
#define NW 8
#define NE 16

// ---------------------------------------------------------------------------
// Static device scratch (allocation forbidden)
// ---------------------------------------------------------------------------
__device__ float g_v[(size_t)PM * (3 * PH)];                 // 8192 x 3072
__device__ float g_q[(size_t)PM * (4 * PH)];                 // 8192 x 4096 (states)
__device__ float g_wr[(size_t)PD * (4 * PH)];                // rna-rounded W_out
__device__ __half g_ah[(size_t)PM * (2 * PD)];               // x fp16 [hi|lo]
__device__ __half g_bh[(size_t)(3 * PH) * (2 * PD)];         // W_in fp16 [hi|lo]
__device__ float g_sub[(size_t)PB * NC * NW * PH * 4];       // sub aggregates
__device__ float g_part[(size_t)PB * NC * PH * 4];           // chunk TOTALS

// ---------------------------------------------------------------------------
// Helpers
// ---------------------------------------------------------------------------
__device__ __forceinline__ uint32_t smem_u32(const void* p) {
    uint32_t a;
    asm("{ .reg .u64 t; cvta.to.shared.u64 t, %1; cvt.u32.u64 %0, t; }" : "=r"(a) : "l"(p));
    return a;
}
__device__ __forceinline__ float tf32r(float a) {
    float r;
    asm("cvt.rna.tf32.f32 %0, %1;" : "=f"(r) : "f"(a));
    return r;
}
__device__ __forceinline__ float sqrt_approx(float a) {
    float r;
    asm("sqrt.approx.f32 %0, %1;" : "=f"(r) : "f"(a));
    return r;
}
__device__ __forceinline__ void cp_async16(uint32_t dst, const void* src) {
    asm volatile("cp.async.cg.shared.global [%0], [%1], 16;" :: "r"(dst), "l"(src));
}

#define MMA_TF32(acc, a0, a1, a2, a3, b0, b1) \
    asm volatile("mma.sync.aligned.m16n8k8.row.col.f32.tf32.tf32.f32 " \
        "{%0,%1,%2,%3}, {%4,%5,%6,%7}, {%8,%9}, {%0,%1,%2,%3};" \
        : "+f"((acc)[0]), "+f"((acc)[1]), "+f"((acc)[2]), "+f"((acc)[3]) \
        : "r"(a0), "r"(a1), "r"(a2), "r"(a3), "r"(b0), "r"(b1))

#define MMA_F16F32(acc, a0, a1, a2, a3, b0, b1) \
    asm volatile("mma.sync.aligned.m16n8k16.row.col.f32.f16.f16.f32 " \
        "{%0,%1,%2,%3}, {%4,%5,%6,%7}, {%8,%9}, {%0,%1,%2,%3};" \
        : "+f"((acc)[0]), "+f"((acc)[1]), "+f"((acc)[2]), "+f"((acc)[3]) \
        : "r"(a0), "r"(a1), "r"(a2), "r"(a3), "r"(b0), "r"(b1))

#define MMA_F16F16(d, a0, a1, a2, a3, b0, b1) \
    asm volatile("mma.sync.aligned.m16n8k16.row.col.f16.f16.f16.f16 " \
        "{%0,%1}, {%2,%3,%4,%5}, {%6,%7}, {%0,%1};" \
        : "+r"((d)[0]), "+r"((d)[1]) \
        : "r"(a0), "r"(a1), "r"(a2), "r"(a3), "r"(b0), "r"(b1))

// ---------------------------------------------------------------------------
// Shared GEMM geometry: CTA 128x128, 8 warps 2Mx4N of 64x32, 3-stage
// cp.async, XOR swizzle. (round-12 proven config)
// ---------------------------------------------------------------------------
#define BM 128
#define BN 128
#define GSTAGES 3
#define STAGE_BYTES 32768          // A 16KB + B 16KB
#define GSMEM (GSTAGES * STAGE_BYTES)

// fragment addressing setup (identical for all b16-element GEMMs)
#define FRAG_SETUP() \
    const int aHalf = lane >> 4; \
    uint32_t aOff[4], aSwz[4]; \
    _Pragma("unroll") \
    for (int mt = 0; mt < 4; mt++) { \
        int r = wm * 64 + mt * 16 + (lane & 15); \
        aOff[mt] = r * 128; \
        aSwz[mt] = r & 7; \
    } \
    const int bHalf = (lane >> 3) & 1; \
    uint32_t bOff[2], bSwz[2]; \
    _Pragma("unroll") \
    for (int ntp = 0; ntp < 2; ntp++) { \
        int r = wn * 32 + ntp * 16 + (lane & 7) + ((lane >> 4) << 3); \
        bOff[ntp] = r * 128; \
        bSwz[ntp] = r & 7; \
    }

#define LOAD_FRAGS(sA, sB, ks, aF, bF) \
    _Pragma("unroll") \
    for (int mt = 0; mt < 4; mt++) { \
        uint32_t ad = (sA) + aOff[mt] + (((2 * (ks) + aHalf) ^ aSwz[mt]) << 4); \
        asm volatile("ldmatrix.sync.aligned.m8n8.x4.shared.b16 {%0,%1,%2,%3}, [%4];" \
            : "=r"((aF)[mt][0]), "=r"((aF)[mt][1]), "=r"((aF)[mt][2]), "=r"((aF)[mt][3]) \
            : "r"(ad)); \
    } \
    _Pragma("unroll") \
    for (int ntp = 0; ntp < 2; ntp++) { \
        uint32_t bd = (sB) + bOff[ntp] + (((2 * (ks) + bHalf) ^ bSwz[ntp]) << 4); \
        asm volatile("ldmatrix.sync.aligned.m8n8.x4.shared.b16 {%0,%1,%2,%3}, [%4];" \
            : "=r"((bF)[2 * ntp][0]), "=r"((bF)[2 * ntp][1]), \
              "=r"((bF)[2 * ntp + 1][0]), "=r"((bF)[2 * ntp + 1][1]) \
            : "r"(bd)); \
    }

// ---------------------------------------------------------------------------
// GEMM1 (fp16 mixed-accumulator 3-term):
//   C = a*b with a = ah+al, b = bh+bl (fp16 split, K=1024 each)
//   phase 1 (vk 0..31):  al*bh + ah*bl  with f16 accumulators
//   phase 2 (vk 32..47): ah*bh          with f32 accumulators (init from phase 1)
// A2: [8192 x 2048] f16 rows = [hi(1024) | lo(1024)], B2: [3072 x 2048] same.
// ---------------------------------------------------------------------------
#define G1_T 48

__device__ __forceinline__ void vkmap(int vk, uint32_t& aoff, uint32_t& boff) {
    if (vk < 16)      { aoff = 2048u + vk * 128u;        boff = vk * 128u; }          // lo_a * hi_b
    else if (vk < 32) { aoff = (vk - 16) * 128u;         boff = 2048u + (vk - 16) * 128u; } // hi_a * lo_b
    else              { aoff = (vk - 32) * 128u;         boff = (vk - 32) * 128u; }   // hi_a * hi_b
}

__global__ __launch_bounds__(256)
void gemm1_f16(const __half* __restrict__ A2, const __half* __restrict__ B2,
               const float* __restrict__ bias, float* __restrict__ C) {
    extern __shared__ char smem[];
    const uint32_t sbase = smem_u32(smem);
    const int N = 3 * PH;

    const int tid = threadIdx.x;
    const int lane = tid & 31;
    const int wid = tid >> 5;
    const int wm = wid & 1;
    const int wn = wid >> 1;
    const int crow = blockIdx.y * BM;
    const int ccol = blockIdx.x * BN;

    const char* Abase = (const char*)(A2 + (size_t)crow * 2048);
    const char* Bbase = (const char*)(B2 + (size_t)ccol * 2048);

    FRAG_SETUP();

    uint32_t accH[4][4][2];
    float accC[4][4][4];
#pragma unroll
    for (int mt = 0; mt < 4; mt++)
#pragma unroll
        for (int nt = 0; nt < 4; nt++) { accH[mt][nt][0] = 0u; accH[mt][nt][1] = 0u; }

#define ISSUE1(vk, stg) do { \
    uint32_t _ao, _bo; vkmap((vk), _ao, _bo); \
    _Pragma("unroll") \
    for (int _i = 0; _i < 4; _i++) { \
        int _s = tid + _i * 256; \
        int _row = _s >> 3, _c16 = _s & 7; \
        uint32_t _off = _row * 128 + ((_c16 ^ (_row & 7)) << 4); \
        cp_async16(sbase + (stg) * STAGE_BYTES + _off, \
                   Abase + (size_t)_row * 4096 + _ao + _c16 * 16); \
        cp_async16(sbase + (stg) * STAGE_BYTES + 16384 + _off, \
                   Bbase + (size_t)_row * 4096 + _bo + _c16 * 16); \
    } \
} while (0)

    ISSUE1(0, 0);
    asm volatile("cp.async.commit_group;" ::: "memory");
    ISSUE1(1, 1);
    asm volatile("cp.async.commit_group;" ::: "memory");

    for (int vk = 0; vk < G1_T; ++vk) {
        asm volatile("cp.async.wait_group 1;" ::: "memory");
        __syncthreads();
        if (vk + 2 < G1_T) ISSUE1(vk + 2, (vk + 2) % GSTAGES);
        asm volatile("cp.async.commit_group;" ::: "memory");

        if (vk == 32) {
            // fold f16 correction accumulators into f32 accumulators
#pragma unroll
            for (int mt = 0; mt < 4; mt++)
#pragma unroll
                for (int nt = 0; nt < 4; nt++) {
                    __half2 h0 = *(__half2*)&accH[mt][nt][0];
                    __half2 h1 = *(__half2*)&accH[mt][nt][1];
                    float2 f0 = __half22float2(h0);
                    float2 f1 = __half22float2(h1);
                    accC[mt][nt][0] = f0.x; accC[mt][nt][1] = f0.y;
                    accC[mt][nt][2] = f1.x; accC[mt][nt][3] = f1.y;
                }
        }

        const uint32_t sA = sbase + (vk % GSTAGES) * STAGE_BYTES;
        const uint32_t sB = sA + 16384;
#pragma unroll
        for (int ks = 0; ks < 4; ks++) {
            uint32_t aF[4][4];
            uint32_t bF[4][2];
            LOAD_FRAGS(sA, sB, ks, aF, bF);
            if (vk < 32) {
#pragma unroll
                for (int mt = 0; mt < 4; mt++)
#pragma unroll
                    for (int nt = 0; nt < 4; nt++)
                        MMA_F16F16(accH[mt][nt], aF[mt][0], aF[mt][1], aF[mt][2], aF[mt][3],
                                   bF[nt][0], bF[nt][1]);
            } else {
#pragma unroll
                for (int mt = 0; mt < 4; mt++)
#pragma unroll
                    for (int nt = 0; nt < 4; nt++)
                        MMA_F16F32(accC[mt][nt], aF[mt][0], aF[mt][1], aF[mt][2], aF[mt][3],
                                   bF[nt][0], bF[nt][1]);
            }
        }
    }

    const int g = lane >> 2, tg = lane & 3;
#pragma unroll
    for (int mt = 0; mt < 4; mt++) {
        int r0 = crow + wm * 64 + mt * 16 + g;
#pragma unroll
        for (int nt = 0; nt < 4; nt++) {
            int col = ccol + wn * 32 + nt * 8 + 2 * tg;
            float2 bv = *(const float2*)(bias + col);
            float2 o0 = make_float2(accC[mt][nt][0] + bv.x, accC[mt][nt][1] + bv.y);
            float2 o1 = make_float2(accC[mt][nt][2] + bv.x, accC[mt][nt][3] + bv.y);
            *(float2*)(C + (size_t)r0 * N + col) = o0;
            *(float2*)(C + (size_t)(r0 + 8) * N + col) = o1;
        }
    }
#undef ISSUE1
}

// ---------------------------------------------------------------------------
// GEMM2 (tf32 single-pass, round-12 proven): C = A*B^T + bias, K in elements.
// ---------------------------------------------------------------------------
__global__ __launch_bounds__(256)
void gemm2_tf32(const float* __restrict__ A, const float* __restrict__ B,
                const float* __restrict__ bias, float* __restrict__ C,
                int N, int K) {
    extern __shared__ char smem[];
    const uint32_t sbase = smem_u32(smem);
    const int KE = 32;
    const int T = K / KE;

    const int tid = threadIdx.x;
    const int lane = tid & 31;
    const int wid = tid >> 5;
    const int wm = wid & 1;
    const int wn = wid >> 1;
    const int crow = blockIdx.y * BM;
    const int ccol = blockIdx.x * BN;

    const size_t rowBytes = (size_t)K * 4;
    const char* Abase = (const char*)A + (size_t)crow * rowBytes;
    const char* Bbase = (const char*)B + (size_t)ccol * rowBytes;

    FRAG_SETUP();

    float acc[4][4][4];
#pragma unroll
    for (int mt = 0; mt < 4; mt++)
#pragma unroll
        for (int nt = 0; nt < 4; nt++)
#pragma unroll
            for (int j = 0; j < 4; j++) acc[mt][nt][j] = 0.0f;

#define ISSUE2(kt, stg) do { \
    _Pragma("unroll") \
    for (int _i = 0; _i < 4; _i++) { \
        int _s = tid + _i * 256; \
        int _row = _s >> 3, _c16 = _s & 7; \
        uint32_t _off = _row * 128 + ((_c16 ^ (_row & 7)) << 4); \
        cp_async16(sbase + (stg) * STAGE_BYTES + _off, \
                   Abase + (size_t)_row * rowBytes + (kt) * 128 + _c16 * 16); \
        cp_async16(sbase + (stg) * STAGE_BYTES + 16384 + _off, \
                   Bbase + (size_t)_row * rowBytes + (kt) * 128 + _c16 * 16); \
    } \
} while (0)

    ISSUE2(0, 0);
    asm volatile("cp.async.commit_group;" ::: "memory");
    ISSUE2(1, 1);
    asm volatile("cp.async.commit_group;" ::: "memory");

    for (int it = 0; it < T; ++it) {
        asm volatile("cp.async.wait_group 1;" ::: "memory");
        __syncthreads();
        if (it + 2 < T) ISSUE2(it + 2, (it + 2) % GSTAGES);
        asm volatile("cp.async.commit_group;" ::: "memory");

        const uint32_t sA = sbase + (it % GSTAGES) * STAGE_BYTES;
        const uint32_t sB = sA + 16384;
#pragma unroll
        for (int ks = 0; ks < 4; ks++) {
            uint32_t aF[4][4];
            uint32_t bF[4][2];
            LOAD_FRAGS(sA, sB, ks, aF, bF);
#pragma unroll
            for (int mt = 0; mt < 4; mt++)
#pragma unroll
                for (int nt = 0; nt < 4; nt++)
                    MMA_TF32(acc[mt][nt], aF[mt][0], aF[mt][1], aF[mt][2], aF[mt][3],
                             bF[nt][0], bF[nt][1]);
        }
    }

    const int g = lane >> 2, tg = lane & 3;
#pragma unroll
    for (int mt = 0; mt < 4; mt++) {
        int r0 = crow + wm * 64 + mt * 16 + g;
#pragma unroll
        for (int nt = 0; nt < 4; nt++) {
            int col = ccol + wn * 32 + nt * 8 + 2 * tg;
            float2 bv = *(const float2*)(bias + col);
            float2 o0 = make_float2(acc[mt][nt][0] + bv.x, acc[mt][nt][1] + bv.y);
            float2 o1 = make_float2(acc[mt][nt][2] + bv.x, acc[mt][nt][3] + bv.y);
            *(float2*)(C + (size_t)r0 * N + col) = o0;
            *(float2*)(C + (size_t)(r0 + 8) * N + col) = o1;
        }
    }
#undef ISSUE2
}

// ---------------------------------------------------------------------------
// Fused prep kernel: region 0 = x fp16 [hi|lo] split, region 1 = W_in fp16
// [hi|lo] split, region 2 = W_out rna-tf32 round.
// ---------------------------------------------------------------------------
#define PREP_T0 ((size_t)PM * PD / 4)              // 2,097,152
#define PREP_T1 ((size_t)(3 * PH) * PD / 4)        //   786,432
#define PREP_T2 ((size_t)PD * (4 * PH) / 4)        // 1,048,576
#define PREP_TOTAL (PREP_T0 + PREP_T1 + PREP_T2)

__device__ __forceinline__ void split_f16_one(const float* __restrict__ in,
                                              __half* __restrict__ out,
                                              int K, size_t s) {
    int K4 = K >> 2;
    size_t row = s / K4;
    int c4 = (int)(s - row * K4);
    float4 a = ((const float4*)in)[s];
    float av[4] = {a.x, a.y, a.z, a.w};
    __half h[4], l[4];
#pragma unroll
    for (int i = 0; i < 4; i++) {
        h[i] = __float2half_rn(av[i]);
        l[i] = __float2half_rn(av[i] - __half2float(h[i]));
    }
    __half* orow = out + row * (size_t)(2 * K);
    __half2* ph = (__half2*)(orow + c4 * 4);
    __half2* pl = (__half2*)(orow + K + c4 * 4);
    ph[0] = __halves2half2(h[0], h[1]); ph[1] = __halves2half2(h[2], h[3]);
    pl[0] = __halves2half2(l[0], l[1]); pl[1] = __halves2half2(l[2], l[3]);
}

__global__ __launch_bounds__(256)
void prep_kernel(const float* __restrict__ x, const float* __restrict__ W_in,
                 const float* __restrict__ W_out,
                 __half* __restrict__ ah, __half* __restrict__ bh,
                 float* __restrict__ wr) {
    size_t gid = (size_t)blockIdx.x * 256 + threadIdx.x;
    if (gid < PREP_T0) {
        split_f16_one(x, ah, PD, gid);
    } else if (gid < PREP_T0 + PREP_T1) {
        split_f16_one(W_in, bh, PD, gid - PREP_T0);
    } else if (gid < PREP_TOTAL) {
        size_t s = gid - PREP_T0 - PREP_T1;
        float4 a = ((const float4*)W_out)[s];
        float4 r;
        r.x = tf32r(a.x); r.y = tf32r(a.y); r.z = tf32r(a.z); r.w = tf32r(a.w);
        ((float4*)wr)[s] = r;
    }
}

// ---------------------------------------------------------------------------
// Quaternion helpers (float4 = w,x,y,z) — MUFU fast-intrinsic versions.
// ---------------------------------------------------------------------------
__device__ __forceinline__ float4 qmul(float4 a, float4 b) {
    return make_float4(
        a.x * b.x - a.y * b.y - a.z * b.z - a.w * b.w,
        a.x * b.y + a.y * b.x + a.z * b.w - a.w * b.z,
        a.x * b.z - a.y * b.w + a.z * b.x + a.w * b.y,
        a.x * b.w + a.y * b.z - a.z * b.y + a.w * b.x);
}
__device__ __forceinline__ float4 qnorm(float4 a) {
    float n2 = a.x * a.x + a.y * a.y + a.z * a.z + a.w * a.w;
    float s = rsqrtf(n2);
    return make_float4(a.x * s, a.y * s, a.z * s, a.w * s);
}
__device__ __forceinline__ float4 qfromv3(float vx, float vy, float vz) {
    float th = sqrt_approx(vx * vx + vy * vy + vz * vz);
    float sn, cs;
    __sincosf(th, &sn, &cs);
    float inv = __fdividef(sn, th + EPSQ);
    return make_float4(cs, vx * inv, vy * inv, vz * inv);
}

// ---------------------------------------------------------------------------
// Two-phase coalesced quaternion scan (round-12/13 proven).
// ---------------------------------------------------------------------------
__global__ __launch_bounds__(256)
void scanA_kernel(const float* __restrict__ v, float* __restrict__ sub,
                  float* __restrict__ part) {
    const int lane = threadIdx.x & 31;
    const int w    = threadIdx.x >> 5;
    const int hg   = blockIdx.x & 31;
    const int c    = (blockIdx.x >> 5) & (NC - 1);
    const int b    = blockIdx.x >> 9;
    const int h    = hg * 32 + lane;

    float4 agg = make_float4(1.0f, 0.0f, 0.0f, 0.0f);
    {
        const int s0 = c * (NW * NE) + w * NE;
        const float* vp = v + ((size_t)(b * PS + s0)) * (3 * PH) + h * 3;
        for (int i = 0; i < NE; i++) {
            agg = qmul(qfromv3(vp[0], vp[1], vp[2]), agg);
            vp += 3 * PH;
        }
    }
    *(float4*)(sub + ((((size_t)b * NC + c) * NW + w) * PH + h) * 4) = agg;

    __shared__ float4 sb[NW][32];
    sb[w][lane] = agg;
    __syncthreads();
    if (w == 0) {
        float4 tot = sb[0][lane];
#pragma unroll
        for (int j = 1; j < NW; j++) tot = qmul(sb[j][lane], tot);
        *(float4*)(part + (((size_t)b * NC + c) * PH + h) * 4) = tot;
    }
}

__global__ __launch_bounds__(256)
void scanC_kernel(const float* __restrict__ v, const float* __restrict__ sub,
                  const float* __restrict__ part, float* __restrict__ states,
                  float* __restrict__ mfinal) {
    const int lane = threadIdx.x & 31;
    const int w    = threadIdx.x >> 5;
    const int hg   = blockIdx.x & 31;
    const int c    = (blockIdx.x >> 5) & (NC - 1);
    const int b    = blockIdx.x >> 9;
    const int h    = hg * 32 + lane;

    __shared__ float4 pref_sh[32];
    if (w == 0) {
        float4 pref = make_float4(1.0f, 0.0f, 0.0f, 0.0f);
        for (int j = 0; j < c; j++) {
            float4 tot = *(const float4*)(part + (((size_t)b * NC + j) * PH + h) * 4);
            pref = qmul(tot, pref);
        }
        pref_sh[lane] = pref;
    }
    __syncthreads();

    float4 p = pref_sh[lane];
    for (int j = 0; j < w; j++) {
        float4 sj = *(const float4*)(sub + ((((size_t)b * NC + c) * NW + j) * PH + h) * 4);
        p = qmul(sj, p);
    }

    const int s0 = c * (NW * NE) + w * NE;
    const float* vp = v + ((size_t)(b * PS + s0)) * (3 * PH) + h * 3;
    float* sp = states + (((size_t)(b * PS + s0)) * PH + h) * 4;
    for (int i = 0; i < NE; i++) {
        p = qmul(qfromv3(vp[0], vp[1], vp[2]), p);
        float4 oq = qnorm(p);
        *(float4*)sp = make_float4(tf32r(oq.x), tf32r(oq.y), tf32r(oq.z), tf32r(oq.w));
        if (c == NC - 1 && w == NW - 1 && i == NE - 1)
            *(float4*)(mfinal + ((size_t)b * PH + h) * 4) = oq;
        vp += 3 * PH;
        sp += (size_t)PH * 4;
    }
}

// ---------------------------------------------------------------------------
extern "C" void kernel_launch(void* const* d_in, const int* in_sizes, int n_in,
                              void* d_out, int out_size) {
    const float* x     = (const float*)d_in[0];   // (B,S,D)
    const float* W_in  = (const float*)d_in[1];   // (3H, D)
    const float* b_in  = (const float*)d_in[2];   // (3H)
    const float* W_out = (const float*)d_in[3];   // (D, 4H)
    const float* b_out = (const float*)d_in[4];   // (D)
    float* out = (float*)d_out;
    float* full_output = out;                      // (B,S,D)
    float* m_final     = out + (size_t)PM * PD;    // (B,H,4)

    float *v_ptr, *q_ptr, *wr, *subp, *partp;
    __half *ah, *bh;
    cudaGetSymbolAddress((void**)&v_ptr, g_v);
    cudaGetSymbolAddress((void**)&q_ptr, g_q);
    cudaGetSymbolAddress((void**)&wr, g_wr);
    cudaGetSymbolAddress((void**)&ah, g_ah);
    cudaGetSymbolAddress((void**)&bh, g_bh);
    cudaGetSymbolAddress((void**)&subp, g_sub);
    cudaGetSymbolAddress((void**)&partp, g_part);

    cudaFuncSetAttribute(gemm1_f16, cudaFuncAttributeMaxDynamicSharedMemorySize, GSMEM);
    cudaFuncSetAttribute(gemm2_tf32, cudaFuncAttributeMaxDynamicSharedMemorySize, GSMEM);

    // fused prep: x/W_in fp16 [hi|lo] splits + W_out rna rounding
    {
        unsigned grid = (unsigned)((PREP_TOTAL + 255) / 256);
        prep_kernel<<<grid, 256>>>(x, W_in, W_out, ah, bh, wr);
    }
    // GEMM1: v = x W_in^T + b_in  (fp16 mixed-acc 3-term)
    {
        dim3 grid(3 * PH / BN, PM / BM);
        gemm1_f16<<<grid, 256, GSMEM>>>(ah, bh, b_in, v_ptr);
    }
    // two-phase coalesced exp-map + prefix quaternion scan (+ m_final)
    {
        const unsigned gridAC = PB * NC * (PH / 32);   // 2048
        scanA_kernel<<<gridAC, 256>>>(v_ptr, subp, partp);
        scanC_kernel<<<gridAC, 256>>>(v_ptr, subp, partp, q_ptr, m_final);
    }
    // GEMM2: out = states W_out^T + b_out  (M=8192, N=1024, K=4096 tf32)
    {
        dim3 grid(PD / BN, PM / BM);
        gemm2_tf32<<<grid, 256, GSMEM>>>(q_ptr, wr, b_out, full_output, PD, 4 * PH);
    }
}

// round 16
// speedup vs baseline: 1.1056x; 1.1056x over previous
#include <cuda_runtime.h>
#include <cuda_bf16.h>
#include <math.h>
#include <stdint.h>

// Problem shapes (fixed): B=4, S=2048, D=1024, H=1024
#define PB 4
#define PS 2048
#define PD 1024
#define PH 1024
#define PM (PB * PS)          // 8192 rows
#define EPSQ 1e-8f

// scan decomposition: 16 chunks x 8 subs x 16 elements = 2048 = S
#define NC 16
#define NW 8
#define NE 16
#define NHG 32                 // h-groups of 32
#define SCAN_BLOCKS (PB * NC * NHG)   // 2048

// ---------------------------------------------------------------------------
// Static device scratch (allocation forbidden)
// ---------------------------------------------------------------------------
__device__ float g_v[(size_t)PM * (3 * PH)];                 // 8192 x 3072
__device__ float g_q[(size_t)PM * (4 * PH)];                 // 8192 x 4096 (states)
__device__ float g_wr[(size_t)PD * (4 * PH)];                // rna-rounded W_out
__device__ __nv_bfloat16 g_ab[(size_t)PM * (3 * PD)];        // x split [hi|lo|hi]
__device__ __nv_bfloat16 g_bb[(size_t)(3 * PH) * (3 * PD)];  // W_in split [hi|hi|lo]
__device__ float g_part[(size_t)PB * NC * PH * 4];           // chunk TOTALS
__device__ int   g_sync[1 + PB * NC * NHG];                  // [0]=ticket, rest=flags

// ---------------------------------------------------------------------------
// Helpers
// ---------------------------------------------------------------------------
__device__ __forceinline__ uint32_t smem_u32(const void* p) {
    uint32_t a;
    asm("{ .reg .u64 t; cvta.to.shared.u64 t, %1; cvt.u32.u64 %0, t; }" : "=r"(a) : "l"(p));
    return a;
}
__device__ __forceinline__ float tf32r(float a) {
    float r;
    asm("cvt.rna.tf32.f32 %0, %1;" : "=f"(r) : "f"(a));
    return r;
}
__device__ __forceinline__ float sqrt_approx(float a) {
    float r;
    asm("sqrt.approx.f32 %0, %1;" : "=f"(r) : "f"(a));
    return r;
}
__device__ __forceinline__ void cp_async16(uint32_t dst, const void* src) {
    asm volatile("cp.async.cg.shared.global [%0], [%1], 16;" :: "r"(dst), "l"(src));
}

#define MMA_TF32(acc, a0, a1, a2, a3, b0, b1) \
    asm volatile("mma.sync.aligned.m16n8k8.row.col.f32.tf32.tf32.f32 " \
        "{%0,%1,%2,%3}, {%4,%5,%6,%7}, {%8,%9}, {%0,%1,%2,%3};" \
        : "+f"((acc)[0]), "+f"((acc)[1]), "+f"((acc)[2]), "+f"((acc)[3]) \
        : "r"(a0), "r"(a1), "r"(a2), "r"(a3), "r"(b0), "r"(b1))

#define MMA_BF16(acc, a0, a1, a2, a3, b0, b1) \
    asm volatile("mma.sync.aligned.m16n8k16.row.col.f32.bf16.bf16.f32 " \
        "{%0,%1,%2,%3}, {%4,%5,%6,%7}, {%8,%9}, {%0,%1,%2,%3};" \
        : "+f"((acc)[0]), "+f"((acc)[1]), "+f"((acc)[2]), "+f"((acc)[3]) \
        : "r"(a0), "r"(a1), "r"(a2), "r"(a3), "r"(b0), "r"(b1))

// ---------------------------------------------------------------------------
// Unified mma.sync GEMM (round-13 proven config: CTA 128x128, 8 warps 2Mx4N
// of 64x32, 3-stage cp.async, XOR swizzle, 2 CTAs/SM).
//   BF16 == 1: bf16 elements, MMA m16n8k16;  BF16 == 0: fp32/tf32, m16n8k8
// K is in ELEMENTS.
// ---------------------------------------------------------------------------
#define BM 128
#define BN 128
#define GSTAGES 3
#define STAGE_BYTES 32768          // A 16KB + B 16KB
#define GSMEM (GSTAGES * STAGE_BYTES)

template<int BF16>
__global__ __launch_bounds__(256)
void gemm_mma(const char* __restrict__ A, const char* __restrict__ B,
              const float* __restrict__ bias, float* __restrict__ C,
              int N, int K) {
    extern __shared__ char smem[];
    const uint32_t sbase = smem_u32(smem);

    const int ESIZE = BF16 ? 2 : 4;
    const int KE = 128 / ESIZE;
    const int T = K / KE;

    const int tid = threadIdx.x;
    const int lane = tid & 31;
    const int wid = tid >> 5;
    const int wm = wid & 1;
    const int wn = wid >> 1;
    const int crow = blockIdx.y * BM;
    const int ccol = blockIdx.x * BN;

    const size_t rowBytes = (size_t)K * ESIZE;
    const char* Abase = A + (size_t)crow * rowBytes;
    const char* Bbase = B + (size_t)ccol * rowBytes;

    const int aHalf = lane >> 4;
    uint32_t aOff[4], aSwz[4];
#pragma unroll
    for (int mt = 0; mt < 4; mt++) {
        int r = wm * 64 + mt * 16 + (lane & 15);
        aOff[mt] = r * 128;
        aSwz[mt] = r & 7;
    }
    const int bHalf = (lane >> 3) & 1;
    uint32_t bOff[2], bSwz[2];
#pragma unroll
    for (int ntp = 0; ntp < 2; ntp++) {
        int r = wn * 32 + ntp * 16 + (lane & 7) + ((lane >> 4) << 3);
        bOff[ntp] = r * 128;
        bSwz[ntp] = r & 7;
    }

    float acc[4][4][4];
#pragma unroll
    for (int mt = 0; mt < 4; mt++)
#pragma unroll
        for (int nt = 0; nt < 4; nt++)
#pragma unroll
            for (int j = 0; j < 4; j++) acc[mt][nt][j] = 0.0f;

#define ISSUE(kt, stg) do { \
    _Pragma("unroll") \
    for (int _i = 0; _i < 4; _i++) { \
        int _s = tid + _i * 256; \
        int _row = _s >> 3, _c16 = _s & 7; \
        uint32_t _off = _row * 128 + ((_c16 ^ (_row & 7)) << 4); \
        const char* _asrc = Abase + (size_t)_row * rowBytes + (kt) * 128 + _c16 * 16; \
        const char* _bsrc = Bbase + (size_t)_row * rowBytes + (kt) * 128 + _c16 * 16; \
        cp_async16(sbase + (stg) * STAGE_BYTES + _off, _asrc); \
        cp_async16(sbase + (stg) * STAGE_BYTES + 16384 + _off, _bsrc); \
    } \
} while (0)

    ISSUE(0, 0);
    asm volatile("cp.async.commit_group;" ::: "memory");
    ISSUE(1, 1);
    asm volatile("cp.async.commit_group;" ::: "memory");

    for (int it = 0; it < T; ++it) {
        asm volatile("cp.async.wait_group 1;" ::: "memory");
        __syncthreads();
        if (it + 2 < T) ISSUE(it + 2, (it + 2) % GSTAGES);
        asm volatile("cp.async.commit_group;" ::: "memory");

        const uint32_t sA = sbase + (it % GSTAGES) * STAGE_BYTES;
        const uint32_t sB = sA + 16384;
#pragma unroll
        for (int ks = 0; ks < 4; ks++) {
            uint32_t aF[4][4];
#pragma unroll
            for (int mt = 0; mt < 4; mt++) {
                uint32_t ad = sA + aOff[mt] + (((2 * ks + aHalf) ^ aSwz[mt]) << 4);
                asm volatile("ldmatrix.sync.aligned.m8n8.x4.shared.b16 {%0,%1,%2,%3}, [%4];"
                    : "=r"(aF[mt][0]), "=r"(aF[mt][1]), "=r"(aF[mt][2]), "=r"(aF[mt][3])
                    : "r"(ad));
            }
            uint32_t bF[4][2];
#pragma unroll
            for (int ntp = 0; ntp < 2; ntp++) {
                uint32_t bd = sB + bOff[ntp] + (((2 * ks + bHalf) ^ bSwz[ntp]) << 4);
                asm volatile("ldmatrix.sync.aligned.m8n8.x4.shared.b16 {%0,%1,%2,%3}, [%4];"
                    : "=r"(bF[2 * ntp][0]), "=r"(bF[2 * ntp][1]),
                      "=r"(bF[2 * ntp + 1][0]), "=r"(bF[2 * ntp + 1][1])
                    : "r"(bd));
            }
#pragma unroll
            for (int mt = 0; mt < 4; mt++)
#pragma unroll
                for (int nt = 0; nt < 4; nt++) {
                    if constexpr (BF16) {
                        MMA_BF16(acc[mt][nt], aF[mt][0], aF[mt][1], aF[mt][2], aF[mt][3],
                                 bF[nt][0], bF[nt][1]);
                    } else {
                        MMA_TF32(acc[mt][nt], aF[mt][0], aF[mt][1], aF[mt][2], aF[mt][3],
                                 bF[nt][0], bF[nt][1]);
                    }
                }
        }
    }

    const int g = lane >> 2, tg = lane & 3;
#pragma unroll
    for (int mt = 0; mt < 4; mt++) {
        int r0 = crow + wm * 64 + mt * 16 + g;
#pragma unroll
        for (int nt = 0; nt < 4; nt++) {
            int col = ccol + wn * 32 + nt * 8 + 2 * tg;
            float2 bv = *(const float2*)(bias + col);
            float2 o0 = make_float2(acc[mt][nt][0] + bv.x, acc[mt][nt][1] + bv.y);
            float2 o1 = make_float2(acc[mt][nt][2] + bv.x, acc[mt][nt][3] + bv.y);
            *(float2*)(C + (size_t)r0 * N + col) = o0;
            *(float2*)(C + (size_t)(r0 + 8) * N + col) = o1;
        }
    }
#undef ISSUE
}

// ---------------------------------------------------------------------------
// Fused prep kernel: region 0 = x bf16-split [hi|lo|hi], region 1 = W_in
// bf16-split [hi|hi|lo], region 2 = W_out rna-tf32 round.
// Additionally zeroes the scan ticket + flags (graph-replay safe).
// ---------------------------------------------------------------------------
#define PREP_T0 ((size_t)PM * PD / 4)              // 2,097,152
#define PREP_T1 ((size_t)(3 * PH) * PD / 4)        //   786,432
#define PREP_T2 ((size_t)PD * (4 * PH) / 4)        // 1,048,576
#define PREP_TOTAL (PREP_T0 + PREP_T1 + PREP_T2)
#define SYNC_WORDS (1 + PB * NC * NHG)             // 2049

__device__ __forceinline__ void split_bf16_one(const float* __restrict__ in,
                                               __nv_bfloat16* __restrict__ out,
                                               int K, int modeB, size_t s) {
    int K4 = K >> 2;
    size_t row = s / K4;
    int c4 = (int)(s - row * K4);
    float4 a = ((const float4*)in)[s];
    float av[4] = {a.x, a.y, a.z, a.w};
    __nv_bfloat16 h[4], l[4];
#pragma unroll
    for (int i = 0; i < 4; i++) {
        h[i] = __float2bfloat16_rn(av[i]);
        l[i] = __float2bfloat16_rn(av[i] - __bfloat162float(h[i]));
    }
    __nv_bfloat162 hv0, hv1, lv0, lv1;
    hv0.x = h[0]; hv0.y = h[1]; hv1.x = h[2]; hv1.y = h[3];
    lv0.x = l[0]; lv0.y = l[1]; lv1.x = l[2]; lv1.y = l[3];
    __nv_bfloat16* orow = out + row * (size_t)(3 * K);
    __nv_bfloat162* p0 = (__nv_bfloat162*)(orow + c4 * 4);
    __nv_bfloat162* p1 = (__nv_bfloat162*)(orow + K + c4 * 4);
    __nv_bfloat162* p2 = (__nv_bfloat162*)(orow + 2 * K + c4 * 4);
    p0[0] = hv0; p0[1] = hv1;
    if (modeB) { p1[0] = hv0; p1[1] = hv1; p2[0] = lv0; p2[1] = lv1; }
    else       { p1[0] = lv0; p1[1] = lv1; p2[0] = hv0; p2[1] = hv1; }
}

__global__ __launch_bounds__(256)
void prep_kernel(const float* __restrict__ x, const float* __restrict__ W_in,
                 const float* __restrict__ W_out,
                 __nv_bfloat16* __restrict__ ab, __nv_bfloat16* __restrict__ bb,
                 float* __restrict__ wr, int* __restrict__ syncw) {
    size_t gid = (size_t)blockIdx.x * 256 + threadIdx.x;
    if (gid < SYNC_WORDS) syncw[gid] = 0;
    if (gid < PREP_T0) {
        split_bf16_one(x, ab, PD, 0, gid);
    } else if (gid < PREP_T0 + PREP_T1) {
        split_bf16_one(W_in, bb, PD, 1, gid - PREP_T0);
    } else if (gid < PREP_TOTAL) {
        size_t s = gid - PREP_T0 - PREP_T1;
        float4 a = ((const float4*)W_out)[s];
        float4 r;
        r.x = tf32r(a.x); r.y = tf32r(a.y); r.z = tf32r(a.z); r.w = tf32r(a.w);
        ((float4*)wr)[s] = r;
    }
}

// ---------------------------------------------------------------------------
// Quaternion helpers (float4 = w,x,y,z) — MUFU fast-intrinsic versions.
// ---------------------------------------------------------------------------
__device__ __forceinline__ float4 qmul(float4 a, float4 b) {
    return make_float4(
        a.x * b.x - a.y * b.y - a.z * b.z - a.w * b.w,
        a.x * b.y + a.y * b.x + a.z * b.w - a.w * b.z,
        a.x * b.z - a.y * b.w + a.z * b.x + a.w * b.y,
        a.x * b.w + a.y * b.z - a.z * b.y + a.w * b.x);
}
__device__ __forceinline__ float4 qnorm(float4 a) {
    float n2 = a.x * a.x + a.y * a.y + a.z * a.z + a.w * a.w;
    float s = rsqrtf(n2);
    return make_float4(a.x * s, a.y * s, a.z * s, a.w * s);
}
__device__ __forceinline__ float4 qfromv3(float vx, float vy, float vz) {
    float th = sqrt_approx(vx * vx + vy * vy + vz * vz);
    float sn, cs;
    __sincosf(th, &sn, &cs);
    float inv = __fdividef(sn, th + EPSQ);
    return make_float4(cs, vx * inv, vy * inv, vz * inv);
}

// ---------------------------------------------------------------------------
// Fused single-pass quaternion scan with decoupled lookback.
// 2048 blocks x 256 threads (32 h-lanes x NW subs). Ticket-ordered tile
// assignment (c-major) guarantees deadlock freedom: a block for chunk c
// waits only on chunks < c, whose tickets are lower (already running/done).
// sub-aggregates live in smem (no g_sub round-trip); v re-read in phase C
// hits L2 (48KB/block slice).
// ---------------------------------------------------------------------------
__global__ __launch_bounds__(256)
void scan_fused_kernel(const float* __restrict__ v, float* __restrict__ part,
                       int* __restrict__ syncw, float* __restrict__ states,
                       float* __restrict__ mfinal) {
    __shared__ int s_ticket;
    __shared__ float4 sb[NW][32];
    __shared__ float4 pref_sh[32];

    if (threadIdx.x == 0) s_ticket = atomicAdd(&syncw[0], 1);
    __syncthreads();
    const int t    = s_ticket;
    const int c    = t >> 7;           // chunk (c-major: all c=0 first)
    const int r    = t & 127;
    const int b    = r >> 5;
    const int hg   = r & 31;
    const int lane = threadIdx.x & 31;
    const int w    = threadIdx.x >> 5;
    const int h    = hg * 32 + lane;
    int* flags = syncw + 1;

    // phase A: aggregate 16 elements (newest on left)
    float4 agg = make_float4(1.0f, 0.0f, 0.0f, 0.0f);
    const int s0 = c * (NW * NE) + w * NE;
    {
        const float* vp = v + ((size_t)(b * PS + s0)) * (3 * PH) + h * 3;
        for (int i = 0; i < NE; i++) {
            agg = qmul(qfromv3(vp[0], vp[1], vp[2]), agg);
            vp += 3 * PH;
        }
    }
    sb[w][lane] = agg;
    __syncthreads();

    // warp 0: publish chunk total, then lookback for exclusive prefix
    if (w == 0) {
        float4 tot = sb[0][lane];
#pragma unroll
        for (int j = 1; j < NW; j++) tot = qmul(sb[j][lane], tot);
        *(float4*)(part + (((size_t)b * NC + c) * PH + h) * 4) = tot;
        __syncwarp();
        __threadfence();
        if (lane == 0) atomicExch(&flags[(b * NC + c) * NHG + hg], 1);

        float4 pref = make_float4(1.0f, 0.0f, 0.0f, 0.0f);
        for (int j = 0; j < c; j++) {
            if (lane == 0) {
                while (atomicAdd(&flags[(b * NC + j) * NHG + hg], 0) == 0) { }
            }
            __syncwarp();
            __threadfence();
            float4 tj = *(const float4*)(part + (((size_t)b * NC + j) * PH + h) * 4);
            pref = qmul(tj, pref);
        }
        pref_sh[lane] = pref;
    }
    __syncthreads();

    // phase C: prefix = (subs w-1..0, from smem) * chunk exclusive prefix
    float4 p = pref_sh[lane];
    for (int j = 0; j < w; j++) p = qmul(sb[j][lane], p);

    {
        const float* vp = v + ((size_t)(b * PS + s0)) * (3 * PH) + h * 3;
        float* sp = states + (((size_t)(b * PS + s0)) * PH + h) * 4;
        for (int i = 0; i < NE; i++) {
            p = qmul(qfromv3(vp[0], vp[1], vp[2]), p);
            float4 oq = qnorm(p);
            *(float4*)sp = make_float4(tf32r(oq.x), tf32r(oq.y),
                                       tf32r(oq.z), tf32r(oq.w));
            if (c == NC - 1 && w == NW - 1 && i == NE - 1)
                *(float4*)(mfinal + ((size_t)b * PH + h) * 4) = oq;
            vp += 3 * PH;
            sp += (size_t)PH * 4;
        }
    }
}

// ---------------------------------------------------------------------------
extern "C" void kernel_launch(void* const* d_in, const int* in_sizes, int n_in,
                              void* d_out, int out_size) {
    const float* x     = (const float*)d_in[0];   // (B,S,D)
    const float* W_in  = (const float*)d_in[1];   // (3H, D)
    const float* b_in  = (const float*)d_in[2];   // (3H)
    const float* W_out = (const float*)d_in[3];   // (D, 4H)
    const float* b_out = (const float*)d_in[4];   // (D)
    float* out = (float*)d_out;
    float* full_output = out;                      // (B,S,D)
    float* m_final     = out + (size_t)PM * PD;    // (B,H,4)

    float *v_ptr, *q_ptr, *wr, *partp;
    __nv_bfloat16 *ab, *bb;
    int* syncw;
    cudaGetSymbolAddress((void**)&v_ptr, g_v);
    cudaGetSymbolAddress((void**)&q_ptr, g_q);
    cudaGetSymbolAddress((void**)&wr, g_wr);
    cudaGetSymbolAddress((void**)&ab, g_ab);
    cudaGetSymbolAddress((void**)&bb, g_bb);
    cudaGetSymbolAddress((void**)&partp, g_part);
    cudaGetSymbolAddress((void**)&syncw, g_sync);

    cudaFuncSetAttribute(gemm_mma<1>, cudaFuncAttributeMaxDynamicSharedMemorySize, GSMEM);
    cudaFuncSetAttribute(gemm_mma<0>, cudaFuncAttributeMaxDynamicSharedMemorySize, GSMEM);

    // fused prep: splits + W_out rounding + scan sync-word reset
    {
        unsigned grid = (unsigned)((PREP_TOTAL + 255) / 256);
        prep_kernel<<<grid, 256>>>(x, W_in, W_out, ab, bb, wr, syncw);
    }
    // GEMM1: v = x W_in^T + b_in  (M=8192, N=3072, K'=3072 bf16 3-term)
    {
        dim3 grid(3 * PH / BN, PM / BM);
        gemm_mma<1><<<grid, 256, GSMEM>>>((const char*)ab, (const char*)bb,
                                          b_in, v_ptr, 3 * PH, 3 * PD);
    }
    // fused exp-map + prefix quaternion scan with decoupled lookback
    scan_fused_kernel<<<SCAN_BLOCKS, 256>>>(v_ptr, partp, syncw, q_ptr, m_final);
    // GEMM2: out = states W_out^T + b_out  (M=8192, N=1024, K=4096 tf32)
    {
        dim3 grid(PD / BN, PM / BM);
        gemm_mma<0><<<grid, 256, GSMEM>>>((const char*)q_ptr, (const char*)wr,
                                          b_out, full_output, PD, 4 * PH);
    }
}